// round 1
// baseline (speedup 1.0000x reference)
#include <cuda_runtime.h>
#include <math.h>

#define NG    2048
#define W     128
#define H     128
#define NPIX  (W*H)
#define NSEG  8
#define SEGLEN (NG/NSEG)
#define EPSV  1e-4f
#define NEARV 0.3f

// ---------------- device scratch (no allocations allowed) ----------------
__device__ float4 d_up0[NG];   // unsorted: u, v, A(=-0.5*ia), B(=-ib)
__device__ float4 d_up1[NG];   // unsorted: C(=-0.5*ic), opa_eff, rgb.r, rgb.g
__device__ float  d_ub [NG];   // unsorted: rgb.b
__device__ float  d_key[NG];   // depth key r
__device__ int    d_order[NG];
__device__ float4 d_sp0[NG];   // sorted
__device__ float4 d_sp1[NG];
__device__ float  d_sb [NG];
__device__ float4 d_part[NSEG*NPIX]; // per-segment (r,g,b,T)

__device__ __forceinline__ float sigmoidf_(float x) {
    return 1.0f / (1.0f + expf(-x));
}

// ---------------- 1) per-gaussian preprocessing ----------------
__global__ void prep_kernel(const float* __restrict__ pos,
                            const float* __restrict__ rgb,
                            const float* __restrict__ opa,
                            const float* __restrict__ quat,
                            const float* __restrict__ scale,
                            const float* __restrict__ rot,
                            const float* __restrict__ tran)
{
    int n = blockIdx.x * blockDim.x + threadIdx.x;
    if (n >= NG) return;

    float Rw[9];
#pragma unroll
    for (int i = 0; i < 9; i++) Rw[i] = __ldg(&rot[i]);
    float t0 = __ldg(&tran[0]), t1 = __ldg(&tran[1]), t2 = __ldg(&tran[2]);

    float p0 = pos[n*3+0], p1 = pos[n*3+1], p2 = pos[n*3+2];
    float x = Rw[0]*p0 + Rw[1]*p1 + Rw[2]*p2 + t0;
    float y = Rw[3]*p0 + Rw[4]*p1 + Rw[5]*p2 + t1;
    float z = Rw[6]*p0 + Rw[7]*p1 + Rw[8]*p2 + t2;

    float r = sqrtf(x*x + y*y + z*z);
    float iz  = 1.0f / z;
    float u = x * iz, v = y * iz;
    float iz2 = iz * iz;

    // M = first two rows of J @ rot
    float M00 = iz*Rw[0] - x*iz2*Rw[6];
    float M01 = iz*Rw[1] - x*iz2*Rw[7];
    float M02 = iz*Rw[2] - x*iz2*Rw[8];
    float M10 = iz*Rw[3] - y*iz2*Rw[6];
    float M11 = iz*Rw[4] - y*iz2*Rw[7];
    float M12 = iz*Rw[5] - y*iz2*Rw[8];

    // quaternion -> rotation
    float qw = quat[n*4+0], qx = quat[n*4+1], qy = quat[n*4+2], qz = quat[n*4+3];
    float qn = rsqrtf(qw*qw + qx*qx + qy*qy + qz*qz);
    qw *= qn; qx *= qn; qy *= qn; qz *= qn;
    float R00 = 1.0f - 2.0f*(qy*qy + qz*qz);
    float R01 = 2.0f*(qx*qy - qw*qz);
    float R02 = 2.0f*(qx*qz + qw*qy);
    float R10 = 2.0f*(qx*qy + qw*qz);
    float R11 = 1.0f - 2.0f*(qx*qx + qz*qz);
    float R12 = 2.0f*(qy*qz - qw*qx);
    float R20 = 2.0f*(qx*qz - qw*qy);
    float R21 = 2.0f*(qy*qz + qw*qx);
    float R22 = 1.0f - 2.0f*(qx*qx + qy*qy);

    float s0 = fabsf(scale[n*3+0]) + 1e-4f;
    float s1 = fabsf(scale[n*3+1]) + 1e-4f;
    float s2 = fabsf(scale[n*3+2]) + 1e-4f;
    float q0 = s0*s0, q1 = s1*s1, q2 = s2*s2;

    // cov3d = R diag(s^2) R^T (symmetric)
    float c00 = R00*R00*q0 + R01*R01*q1 + R02*R02*q2;
    float c01 = R00*R10*q0 + R01*R11*q1 + R02*R12*q2;
    float c02 = R00*R20*q0 + R01*R21*q1 + R02*R22*q2;
    float c11 = R10*R10*q0 + R11*R11*q1 + R12*R12*q2;
    float c12 = R10*R20*q0 + R11*R21*q1 + R12*R22*q2;
    float c22 = R20*R20*q0 + R21*R21*q1 + R22*R22*q2;

    // v0 = cov3d @ M0, v1 = cov3d @ M1
    float v00 = c00*M00 + c01*M01 + c02*M02;
    float v01 = c01*M00 + c11*M01 + c12*M02;
    float v02 = c02*M00 + c12*M01 + c22*M02;
    float v10 = c00*M10 + c01*M11 + c02*M12;
    float v11 = c01*M10 + c11*M11 + c12*M12;
    float v12 = c02*M10 + c12*M11 + c22*M12;

    float a  = M00*v00 + M01*v01 + M02*v02 + EPSV;
    float b  = M00*v10 + M01*v11 + M02*v12;
    float cc = M10*v10 + M11*v11 + M12*v12 + EPSV;

    float det  = a*cc - b*b;
    float idet = 1.0f / det;
    // power = A*dx^2 + B*dx*dy + C*dy^2
    float A = -0.5f * cc * idet;
    float B =  b * idet;
    float C = -0.5f * a  * idet;

    float opa_eff = sigmoidf_(opa[n]) * (z > NEARV ? 1.0f : 0.0f);
    float cr = sigmoidf_(rgb[n*3+0]);
    float cg = sigmoidf_(rgb[n*3+1]);
    float cb = sigmoidf_(rgb[n*3+2]);

    d_up0[n] = make_float4(u, v, A, B);
    d_up1[n] = make_float4(C, opa_eff, cr, cg);
    d_ub[n]  = cb;
    d_key[n] = r;
}

// ---------------- 2) bitonic argsort of 2048 keys (single block) ----------------
__global__ void sort_kernel()
{
    __shared__ float kr[NG];
    __shared__ int   ki[NG];
    int t = threadIdx.x;
    kr[t]        = d_key[t];        ki[t]        = t;
    kr[t + 1024] = d_key[t + 1024]; ki[t + 1024] = t + 1024;

    for (int k = 2; k <= NG; k <<= 1) {
        for (int j = k >> 1; j > 0; j >>= 1) {
            __syncthreads();
            int i = 2*t - (t & (j - 1));
            int p = i + j;
            bool up = ((i & k) == 0);
            float ka = kr[i], kb = kr[p];
            int   ea = ki[i], eb = ki[p];
            bool gt = (ka > kb) || (ka == kb && ea > eb);
            if (gt == up) {
                kr[i] = kb; kr[p] = ka;
                ki[i] = eb; ki[p] = ea;
            }
        }
    }
    __syncthreads();
    d_order[t]        = ki[t];
    d_order[t + 1024] = ki[t + 1024];
}

// ---------------- 3) gather into sorted order ----------------
__global__ void gather_kernel()
{
    int i = blockIdx.x * blockDim.x + threadIdx.x;
    if (i >= NG) return;
    int j = d_order[i];
    d_sp0[i] = d_up0[j];
    d_sp1[i] = d_up1[j];
    d_sb[i]  = d_ub[j];
}

// ---------------- 4) segmented alpha compositing ----------------
// grid: (64 tiles of 16x16 px, NSEG segments), 256 threads/block
__global__ void __launch_bounds__(256) render_kernel()
{
    __shared__ float4 sm0[SEGLEN];
    __shared__ float4 sm1[SEGLEN];
    __shared__ float  smb[SEGLEN];

    int t    = threadIdx.x;
    int seg  = blockIdx.y;
    int tile = blockIdx.x;

    int base = seg * SEGLEN;
    sm0[t] = d_sp0[base + t];
    sm1[t] = d_sp1[base + t];
    smb[t] = d_sb[base + t];
    __syncthreads();

    // warp -> 8x4 pixel patch for skip coherence; block -> 16x16 tile
    int w = t >> 5, l = t & 31;
    int x = (tile & 7) * 16 + ((w & 1) << 3) + (l & 7);
    int y = (tile >> 3) * 16 + ((w >> 1) << 2) + (l >> 3);
    float px = (x - 63.5f) * (1.0f / 128.0f);
    float py = (y - 63.5f) * (1.0f / 128.0f);

    float T = 1.0f, cr = 0.0f, cg = 0.0f, cb = 0.0f;

#pragma unroll 4
    for (int k = 0; k < SEGLEN; k++) {
        float4 p0 = sm0[k];
        float dx = px - p0.x;
        float dy = py - p0.y;
        float4 p1 = sm1[k];
        float pw = fmaf(fmaf(p0.z, dx, p0.w * dy), dx, p1.x * dy * dy);
        if (pw > -18.0f) {
            float al = fminf(p1.y * __expf(pw), 0.99f);
            float wg = T * al;
            cr = fmaf(wg, p1.z, cr);
            cg = fmaf(wg, p1.w, cg);
            cb = fmaf(wg, smb[k], cb);
            T -= wg;
        }
    }

    int pix = y * W + x;
    d_part[seg * NPIX + pix] = make_float4(cr, cg, cb, T);
}

// ---------------- 5) combine segments ----------------
__global__ void combine_kernel(float* __restrict__ out)
{
    int pix = blockIdx.x * blockDim.x + threadIdx.x;
    if (pix >= NPIX) return;
    float P = 1.0f, r = 0.0f, g = 0.0f, b = 0.0f;
#pragma unroll
    for (int s = 0; s < NSEG; s++) {
        float4 q = d_part[s * NPIX + pix];
        r = fmaf(P, q.x, r);
        g = fmaf(P, q.y, g);
        b = fmaf(P, q.z, b);
        P *= q.w;
    }
    out[pix*3 + 0] = r;
    out[pix*3 + 1] = g;
    out[pix*3 + 2] = b;
}

extern "C" void kernel_launch(void* const* d_in, const int* in_sizes, int n_in,
                              void* d_out, int out_size)
{
    const float* pos   = (const float*)d_in[0];
    const float* rgb   = (const float*)d_in[1];
    const float* opa   = (const float*)d_in[2];
    const float* quat  = (const float*)d_in[3];
    const float* scale = (const float*)d_in[4];
    const float* rot   = (const float*)d_in[5];
    const float* tran  = (const float*)d_in[6];
    float* out = (float*)d_out;

    prep_kernel<<<NG/256, 256>>>(pos, rgb, opa, quat, scale, rot, tran);
    sort_kernel<<<1, 1024>>>();
    gather_kernel<<<NG/256, 256>>>();
    render_kernel<<<dim3(64, NSEG), 256>>>();
    combine_kernel<<<NPIX/256, 256>>>(out);
}